// round 7
// baseline (speedup 1.0000x reference)
#include <cuda_runtime.h>
#include <cuda_fp16.h>
#include <cstdint>
#include <math.h>

// ============================================================================
// DUQ head via HMMA 3xFP16-split GEMM; cross terms use FP16 accumulators
// (potential 2x-rate path), main term fp32 accum.
// out[b,c,p] = exp(-3.125 * sum_e (emb[p, c*16+e] - cent[c*16+e])^2)
// emb = feat[b,:,p].w[n,:], n=c*16+e, K=512.
// a = ah+al, b = bh+bl; acc32 += ah*bh (f32 HMMA); acc16 += ah*bl + al*bh (f16 HMMA).
// CTA tile 256x64, warp tile 64x32 (8 warps/256 thr), BK=32, 4-stage cp.async.
// 64B rows, conflict-free swizzle chunk ^ ((row>>1)&3).
// ============================================================================

#define BM 256
#define BN 64
#define BK 32
#define KTILES 16            // 512 / 32
#define STAGE_BYTES 40960    // Ahi 16K | Alo 16K | Bhi 4K | Blo 4K
#define OFF_ALO 16384
#define OFF_BHI 32768
#define OFF_BLO 36864
#define NSTAGE 4
#define CENT_OFF (NSTAGE * STAGE_BYTES)
#define SMEM_TOTAL (CENT_OFF + 256)

// -------- device-global scratch (no cudaMalloc allowed) ----------------------
__device__ __half g_ah[67108864];   // [131072 px][512 k]
__device__ __half g_al[67108864];
__device__ __half g_bh[524288];     // [1024 n][512 k], n = c*16+e
__device__ __half g_bl[524288];
__device__ float  g_cent[1024];

// -------- helpers -------------------------------------------------------------
__device__ __forceinline__ uint32_t smem_u32(const void* p) {
    uint32_t a;
    asm("{ .reg .u64 t; cvta.to.shared.u64 t, %1; cvt.u32.u64 %0, t; }" : "=r"(a) : "l"(p));
    return a;
}
__device__ __forceinline__ void cp16(uint32_t dst, const __half* src) {
    asm volatile("cp.async.cg.shared.global [%0], [%1], 16;"
                 :: "r"(dst), "l"(__cvta_generic_to_global(src)));
}
__device__ __forceinline__ void ldsm4(uint32_t* r, uint32_t addr) {
    asm volatile("ldmatrix.sync.aligned.m8n8.x4.shared.b16 {%0,%1,%2,%3}, [%4];"
                 : "=r"(r[0]), "=r"(r[1]), "=r"(r[2]), "=r"(r[3]) : "r"(addr));
}
__device__ __forceinline__ void mma_f32(float* c, const uint32_t* a, const uint32_t* b) {
    asm volatile("mma.sync.aligned.m16n8k16.row.col.f32.f16.f16.f32 "
                 "{%0,%1,%2,%3}, {%4,%5,%6,%7}, {%8,%9}, {%0,%1,%2,%3};"
                 : "+f"(c[0]), "+f"(c[1]), "+f"(c[2]), "+f"(c[3])
                 : "r"(a[0]), "r"(a[1]), "r"(a[2]), "r"(a[3]), "r"(b[0]), "r"(b[1]));
}
__device__ __forceinline__ void mma_f16(uint32_t* c, const uint32_t* a, const uint32_t* b) {
    asm volatile("mma.sync.aligned.m16n8k16.row.col.f16.f16.f16.f16 "
                 "{%0,%1}, {%2,%3,%4,%5}, {%6,%7}, {%0,%1};"
                 : "+r"(c[0]), "+r"(c[1])
                 : "r"(a[0]), "r"(a[1]), "r"(a[2]), "r"(a[3]), "r"(b[0]), "r"(b[1]));
}

// -------- prep 1: transpose + fp16-split features ----------------------------
__global__ void prep_feat(const float* __restrict__ feat) {
    __shared__ float tile[32][33];
    int b = blockIdx.z;
    int p0 = blockIdx.x * 32, k0 = blockIdx.y * 32;
    int tx = threadIdx.x, ty = threadIdx.y;                // (32, 8)
    const float* src = feat + ((size_t)b * 512 + k0) * 16384 + p0;
#pragma unroll
    for (int i = 0; i < 4; i++)
        tile[ty + 8 * i][tx] = src[(size_t)(ty + 8 * i) * 16384 + tx];
    __syncthreads();
    size_t dbase = ((size_t)b * 16384 + p0) * 512 + k0;
#pragma unroll
    for (int i = 0; i < 4; i++) {
        int pr = ty + 8 * i;
        float v = tile[tx][pr];
        __half hi = __float2half_rn(v);
        __half lo = __float2half_rn(v - __half2float(hi));
        g_ah[dbase + (size_t)pr * 512 + tx] = hi;
        g_al[dbase + (size_t)pr * 512 + tx] = lo;
    }
}

// -------- prep 2: weights reorder + split, centroids --------------------------
__global__ void prep_w(const float* __restrict__ wgt, const float* __restrict__ m,
                       const float* __restrict__ Nb) {
    int n = blockIdx.x;                 // n = c*16 + e
    int c = n >> 4, e = n & 15;
    const float* src = wgt + ((size_t)e * 64 + c) * 512;
    for (int k = threadIdx.x; k < 512; k += 128) {
        float v = src[k];
        __half hi = __float2half_rn(v);
        g_bh[(size_t)n * 512 + k] = hi;
        g_bl[(size_t)n * 512 + k] = __float2half_rn(v - __half2float(hi));
    }
    if (threadIdx.x == 0) g_cent[n] = m[e * 64 + c] / Nb[c];
}

// -------- stage fill (256 threads): 10 x 16B cp.async per thread ---------------
// 64B rows (4 chunks of 16B), swizzle: chunk ^ ((row>>1)&3)  -> ldsm conflict-free
__device__ __forceinline__ void fill_stage(uint32_t sb, int s, int kt, long P0, int n0, int t) {
    int kb = kt * BK;
    uint32_t st = sb + s * STAGE_BYTES;
    int r = t >> 2, c = t & 3;
#pragma unroll
    for (int i = 0; i < 4; i++) {                 // Ahi / Alo: 256 rows x 4 chunks
        int rr = r + i * 64;
        uint32_t d = st + rr * 64 + (uint32_t)((c ^ ((rr >> 1) & 3)) << 4);
        cp16(d,           g_ah + (size_t)(P0 + rr) * 512 + kb + c * 8);
        cp16(d + OFF_ALO, g_al + (size_t)(P0 + rr) * 512 + kb + c * 8);
    }
    {                                              // Bhi / Blo: 64 rows x 4 chunks
        int rr = r;
        uint32_t d = st + OFF_BHI + rr * 64 + (uint32_t)((c ^ ((rr >> 1) & 3)) << 4);
        cp16(d,                       g_bh + (size_t)(n0 + rr) * 512 + kb + c * 8);
        cp16(d + (OFF_BLO - OFF_BHI), g_bl + (size_t)(n0 + rr) * 512 + kb + c * 8);
    }
}

// -------- main GEMM + fused RBF epilogue ---------------------------------------
__global__ __launch_bounds__(256, 1) void duq_mma(float* __restrict__ out) {
    extern __shared__ char smem[];
    uint32_t sb = smem_u32(smem);
    int t = threadIdx.x, l = t & 31, w = t >> 5;
    int nb = blockIdx.x, mb = blockIdx.y;
    long P0 = (long)mb * BM;           // 256 | 16384 -> never crosses a batch
    int n0 = nb * BN;

    if (t < BN) ((float*)(smem + CENT_OFF))[t] = g_cent[n0 + t];

    int wm = (w >> 1) * 64;            // 4 M-groups of 64
    int wn = (w & 1) * 32;             // 2 N-groups of 32

    int rl  = l & 7;                   // row within 8-row matrix
    int mh  = (l >> 3) & 1;            // matrix half bit
    int hi  = (l >> 4) & 1;            // k-chunk bit

    float    acc[4][4][4];             // main, fp32
    uint32_t acx[4][4][2];             // cross, packed fp16
#pragma unroll
    for (int i = 0; i < 4; i++)
#pragma unroll
        for (int j = 0; j < 4; j++) {
#pragma unroll
            for (int q = 0; q < 4; q++) acc[i][j][q] = 0.0f;
            acx[i][j][0] = 0u; acx[i][j][1] = 0u;
        }

    fill_stage(sb, 0, 0, P0, n0, t);
    asm volatile("cp.async.commit_group;" ::: "memory");
    fill_stage(sb, 1, 1, P0, n0, t);
    asm volatile("cp.async.commit_group;" ::: "memory");
    fill_stage(sb, 2, 2, P0, n0, t);
    asm volatile("cp.async.commit_group;" ::: "memory");

    for (int kt = 0; kt < KTILES; kt++) {
        asm volatile("cp.async.wait_group 2;" ::: "memory");
        __syncthreads();

        if (kt + 3 < KTILES) fill_stage(sb, (kt + 3) % NSTAGE, kt + 3, P0, n0, t);
        asm volatile("cp.async.commit_group;" ::: "memory");

        uint32_t As = sb + (kt % NSTAGE) * STAGE_BYTES;
#pragma unroll
        for (int k16 = 0; k16 < 2; k16++) {
            uint32_t ah[4][4], al[4][4];
#pragma unroll
            for (int mf = 0; mf < 4; mf++) {
                int ra = wm + mf * 16 + mh * 8 + rl;
                uint32_t off = (uint32_t)(ra * 64 + (((2 * k16 + hi) ^ ((ra >> 1) & 3)) << 4));
                ldsm4(ah[mf], As + off);
                ldsm4(al[mf], As + OFF_ALO + off);
            }
#pragma unroll
            for (int np = 0; np < 2; np++) {
                int rb = wn + np * 16 + hi * 8 + rl;
                uint32_t off = (uint32_t)(rb * 64 + (((2 * k16 + mh) ^ ((rb >> 1) & 3)) << 4));
                uint32_t bh4[4], bl4[4];
                ldsm4(bh4, As + OFF_BHI + off);
                ldsm4(bl4, As + OFF_BLO + off);
#pragma unroll
                for (int mf = 0; mf < 4; mf++) {
#pragma unroll
                    for (int h = 0; h < 2; h++) {
                        int nf = 2 * np + h;
                        mma_f32(acc[mf][nf], ah[mf], &bh4[2 * h]);   // ah*bh (f32 acc)
                        mma_f16(acx[mf][nf], ah[mf], &bl4[2 * h]);   // ah*bl (f16 acc)
                        mma_f16(acx[mf][nf], al[mf], &bh4[2 * h]);   // al*bh (f16 acc)
                    }
                }
            }
        }
    }

    // ---- fold fp16 cross accumulators into fp32 main ----
#pragma unroll
    for (int mf = 0; mf < 4; mf++)
#pragma unroll
        for (int nf = 0; nf < 4; nf++) {
            __half2 d0 = *(__half2*)&acx[mf][nf][0];
            __half2 d1 = *(__half2*)&acx[mf][nf][1];
            acc[mf][nf][0] += __low2float(d0);
            acc[mf][nf][1] += __high2float(d0);
            acc[mf][nf][2] += __low2float(d1);
            acc[mf][nf][3] += __high2float(d1);
        }

    // ---- epilogue: diff^2, 16-e reduction (2 quad shuffles), expf, store ----
    const float* centS = (const float*)(smem + CENT_OFF);
    int q2 = l & 3;
    int cbase = (n0 + wn) >> 4;        // first of this warp's 2 channels

#pragma unroll
    for (int mf = 0; mf < 4; mf++) {
        float s[2][2] = {{0.0f, 0.0f}, {0.0f, 0.0f}};   // [channel-half][row-half]
#pragma unroll
        for (int nf = 0; nf < 4; nf++) {
            int q = nf >> 1;
#pragma unroll
            for (int j = 0; j < 2; j++) {
                float ce = centS[wn + nf * 8 + 2 * q2 + j];
                float d0 = acc[mf][nf][j]     - ce;
                float d1 = acc[mf][nf][2 + j] - ce;
                s[q][0] = fmaf(d0, d0, s[q][0]);
                s[q][1] = fmaf(d1, d1, s[q][1]);
            }
        }
#pragma unroll
        for (int q = 0; q < 2; q++)
#pragma unroll
            for (int r = 0; r < 2; r++) {
                s[q][r] += __shfl_xor_sync(0xFFFFFFFFu, s[q][r], 1);
                s[q][r] += __shfl_xor_sync(0xFFFFFFFFu, s[q][r], 2);
            }
        float va = (l & 1) ? s[1][0] : s[0][0];
        float vb = (l & 1) ? s[1][1] : s[0][1];
        float v  = (l & 2) ? vb : va;
        float o  = expf(-3.125f * v);

        long gp = P0 + wm + mf * 16 + ((l >> 2) & 7) + ((l & 2) << 2);
        int b   = (int)(gp >> 14);
        int pin = (int)(gp & 16383);
        int ch  = cbase + (l & 1);
        out[((size_t)b * 64 + ch) * 16384 + pin] = o;
    }
}

// -------- launch ----------------------------------------------------------------
extern "C" void kernel_launch(void* const* d_in, const int* in_sizes, int n_in,
                              void* d_out, int out_size)
{
    const float* feat = (const float*)d_in[0];   // [8, 512, 128, 128]
    const float* wgt  = (const float*)d_in[1];   // [16, 64, 512]
    const float* m    = (const float*)d_in[2];   // [16, 64]
    const float* N    = (const float*)d_in[3];   // [64]
    float* out        = (float*)d_out;           // [8, 64, 128, 128]

    cudaFuncSetAttribute(duq_mma, cudaFuncAttributeMaxDynamicSharedMemorySize, SMEM_TOTAL);

    prep_feat<<<dim3(512, 16, 8), dim3(32, 8)>>>(feat);
    prep_w<<<1024, 128>>>(wgt, m, N);
    duq_mma<<<dim3(16, 512), 256, SMEM_TOTAL>>>(out);
}

// round 8
// speedup vs baseline: 1.2615x; 1.2615x over previous
#include <cuda_runtime.h>
#include <cuda_fp16.h>
#include <cstdint>
#include <math.h>

// ============================================================================
// DUQ head via HMMA 3xFP16-split GEMM, single-pass shared-operand form,
// occupancy-2 geometry (2 CTAs/SM).
// out[b,c,p] = exp(-3.125 * sum_e (emb[p, c*16+e] - cent[c*16+e])^2)
// emb = feat[b,:,p].w[n,:], n=c*16+e, K=512.
// a = ah+al, b = bh+bl (exact fp16 splits); acc += ah*bh + ah*bl + al*bh (f32).
// CTA tile 128x128, warp tile 32x64 (8 warps/256 thr), BK=32,
// 3-stage cp.async, 32KB/stage -> 96KB smem, ~116 regs -> 2 CTAs/SM.
// ============================================================================

#define BM 128
#define BN 128
#define BK 32
#define KTILES 16            // 512 / 32
#define STAGE_BYTES 32768    // Ahi 8K | Alo 8K | Bhi 8K | Blo 8K
#define OFF_ALO 8192
#define OFF_BHI 16384
#define OFF_BLO 24576
#define CENT_OFF (3 * STAGE_BYTES)
#define SMEM_TOTAL (CENT_OFF + 512)

// -------- device-global scratch (no cudaMalloc allowed) ----------------------
__device__ __half g_ah[67108864];   // [131072 px][512 k]
__device__ __half g_al[67108864];
__device__ __half g_bh[524288];     // [1024 n][512 k], n = c*16+e
__device__ __half g_bl[524288];
__device__ float  g_cent[1024];

// -------- helpers -------------------------------------------------------------
__device__ __forceinline__ uint32_t smem_u32(const void* p) {
    uint32_t a;
    asm("{ .reg .u64 t; cvta.to.shared.u64 t, %1; cvt.u32.u64 %0, t; }" : "=r"(a) : "l"(p));
    return a;
}
__device__ __forceinline__ void cp16(uint32_t dst, const __half* src) {
    asm volatile("cp.async.cg.shared.global [%0], [%1], 16;"
                 :: "r"(dst), "l"(__cvta_generic_to_global(src)));
}
__device__ __forceinline__ void ldsm4(uint32_t* r, uint32_t addr) {
    asm volatile("ldmatrix.sync.aligned.m8n8.x4.shared.b16 {%0,%1,%2,%3}, [%4];"
                 : "=r"(r[0]), "=r"(r[1]), "=r"(r[2]), "=r"(r[3]) : "r"(addr));
}
__device__ __forceinline__ void mma_f32(float* c, const uint32_t* a, const uint32_t* b) {
    asm volatile("mma.sync.aligned.m16n8k16.row.col.f32.f16.f16.f32 "
                 "{%0,%1,%2,%3}, {%4,%5,%6,%7}, {%8,%9}, {%0,%1,%2,%3};"
                 : "+f"(c[0]), "+f"(c[1]), "+f"(c[2]), "+f"(c[3])
                 : "r"(a[0]), "r"(a[1]), "r"(a[2]), "r"(a[3]), "r"(b[0]), "r"(b[1]));
}

// -------- prep 1: transpose + fp16-split features (half2 coalesced writes) ----
__global__ void prep_feat(const float* __restrict__ feat) {
    __shared__ float tile[32][65];     // [p][k], padded
    int b  = blockIdx.z;
    int p0 = blockIdx.x * 32, k0 = blockIdx.y * 64;
    int tx = threadIdx.x, ty = threadIdx.y;                // (32, 8)
    const float* src = feat + ((size_t)b * 512 + k0) * 16384 + p0;
#pragma unroll
    for (int i = 0; i < 8; i++) {
        int kr = ty + 8 * i;
        tile[tx][kr] = src[(size_t)kr * 16384 + tx];
    }
    __syncthreads();
    size_t dbase = ((size_t)b * 16384 + p0) * 512 + k0;
#pragma unroll
    for (int j = 0; j < 4; j++) {
        int pr = ty + 8 * j;
        float v0 = tile[pr][2 * tx];
        float v1 = tile[pr][2 * tx + 1];
        __half h0 = __float2half_rn(v0);
        __half h1 = __float2half_rn(v1);
        __half l0 = __float2half_rn(v0 - __half2float(h0));
        __half l1 = __float2half_rn(v1 - __half2float(h1));
        size_t off = dbase + (size_t)pr * 512 + 2 * tx;
        *(__half2*)(g_ah + off) = __halves2half2(h0, h1);
        *(__half2*)(g_al + off) = __halves2half2(l0, l1);
    }
}

// -------- prep 2: weights reorder + split, centroids --------------------------
__global__ void prep_w(const float* __restrict__ wgt, const float* __restrict__ m,
                       const float* __restrict__ Nb) {
    int n = blockIdx.x;                 // n = c*16 + e
    int c = n >> 4, e = n & 15;
    const float* src = wgt + ((size_t)e * 64 + c) * 512;
    for (int k = threadIdx.x; k < 512; k += 128) {
        float v = src[k];
        __half hi = __float2half_rn(v);
        g_bh[(size_t)n * 512 + k] = hi;
        g_bl[(size_t)n * 512 + k] = __float2half_rn(v - __half2float(hi));
    }
    if (threadIdx.x == 0) g_cent[n] = m[e * 64 + c] / Nb[c];
}

// -------- stage fill (256 threads): 8 x 16B cp.async per thread ----------------
// 64B rows (4 chunks of 16B), swizzle chunk ^ ((row>>1)&3) -> ldsm conflict-free
__device__ __forceinline__ void fill_stage(uint32_t sb, int s, int kt, long P0, int n0, int t) {
    int kb = kt * BK;
    uint32_t st = sb + s * STAGE_BYTES;
    int r = t >> 2, c = t & 3;
#pragma unroll
    for (int i = 0; i < 2; i++) {
        int rr = r + i * 64;
        uint32_t d = st + rr * 64 + (uint32_t)((c ^ ((rr >> 1) & 3)) << 4);
        size_t asrc = (size_t)(P0 + rr) * 512 + kb + c * 8;
        size_t bsrc = (size_t)(n0 + rr) * 512 + kb + c * 8;
        cp16(d,           g_ah + asrc);
        cp16(d + OFF_ALO, g_al + asrc);
        cp16(d + OFF_BHI, g_bh + bsrc);
        cp16(d + OFF_BLO, g_bl + bsrc);
    }
}

// -------- main GEMM + fused RBF epilogue ---------------------------------------
__global__ __launch_bounds__(256, 2) void duq_mma(float* __restrict__ out) {
    extern __shared__ char smem[];
    uint32_t sb = smem_u32(smem);
    int t = threadIdx.x, l = t & 31, w = t >> 5;
    int nb = blockIdx.x, mb = blockIdx.y;
    long P0 = (long)mb * BM;           // 128 | 16384 -> never crosses a batch
    int n0 = nb * BN;

    if (t < BN) ((float*)(smem + CENT_OFF))[t] = g_cent[n0 + t];

    int wm = (w >> 1) * 32;            // 4 M-groups of 32
    int wn = (w & 1) * 64;             // 2 N-groups of 64

    int rl  = l & 7;                   // row within 8-row matrix
    int mh  = (l >> 3) & 1;            // matrix half bit
    int hi  = (l >> 4) & 1;            // k-chunk bit

    float acc[2][8][4];
#pragma unroll
    for (int i = 0; i < 2; i++)
#pragma unroll
        for (int j = 0; j < 8; j++)
#pragma unroll
            for (int q = 0; q < 4; q++) acc[i][j][q] = 0.0f;

    fill_stage(sb, 0, 0, P0, n0, t);
    asm volatile("cp.async.commit_group;" ::: "memory");
    fill_stage(sb, 1, 1, P0, n0, t);
    asm volatile("cp.async.commit_group;" ::: "memory");

    for (int kt = 0; kt < KTILES; kt++) {
        asm volatile("cp.async.wait_group 1;" ::: "memory");
        __syncthreads();

        if (kt + 2 < KTILES) fill_stage(sb, (kt + 2) % 3, kt + 2, P0, n0, t);
        asm volatile("cp.async.commit_group;" ::: "memory");

        uint32_t As = sb + (kt % 3) * STAGE_BYTES;
#pragma unroll
        for (int k16 = 0; k16 < 2; k16++) {
            uint32_t ah[2][4], al[2][4];
#pragma unroll
            for (int mf = 0; mf < 2; mf++) {
                int ra = wm + mf * 16 + mh * 8 + rl;
                uint32_t off = (uint32_t)(ra * 64 + (((2 * k16 + hi) ^ ((ra >> 1) & 3)) << 4));
                ldsm4(ah[mf], As + off);
                ldsm4(al[mf], As + OFF_ALO + off);
            }
#pragma unroll
            for (int np = 0; np < 4; np++) {
                int rb = wn + np * 16 + hi * 8 + rl;
                uint32_t off = (uint32_t)(rb * 64 + (((2 * k16 + mh) ^ ((rb >> 1) & 3)) << 4));
                uint32_t bh4[4], bl4[4];
                ldsm4(bh4, As + OFF_BHI + off);
                ldsm4(bl4, As + OFF_BLO + off);
#pragma unroll
                for (int mf = 0; mf < 2; mf++) {
#pragma unroll
                    for (int h = 0; h < 2; h++) {
                        int nf = 2 * np + h;
                        mma_f32(acc[mf][nf], ah[mf], &bh4[2 * h]);
                        mma_f32(acc[mf][nf], ah[mf], &bl4[2 * h]);
                        mma_f32(acc[mf][nf], al[mf], &bh4[2 * h]);
                    }
                }
            }
        }
    }

    // ---- epilogue: diff^2, 16-e reduction (2 quad shuffles), expf, store ----
    const float* centS = (const float*)(smem + CENT_OFF);
    int q2 = l & 3;
    int cb = (n0 + wn) >> 4;           // first of this warp's 4 channels

#pragma unroll
    for (int mf = 0; mf < 2; mf++) {
        float s[4][2];
#pragma unroll
        for (int ch = 0; ch < 4; ch++) { s[ch][0] = 0.0f; s[ch][1] = 0.0f; }
#pragma unroll
        for (int nf = 0; nf < 8; nf++) {
            int ch = nf >> 1;
#pragma unroll
            for (int j = 0; j < 2; j++) {
                float ce = centS[wn + nf * 8 + 2 * q2 + j];
                float d0 = acc[mf][nf][j]     - ce;
                float d1 = acc[mf][nf][2 + j] - ce;
                s[ch][0] = fmaf(d0, d0, s[ch][0]);
                s[ch][1] = fmaf(d1, d1, s[ch][1]);
            }
        }
#pragma unroll
        for (int ch = 0; ch < 4; ch++)
#pragma unroll
            for (int r = 0; r < 2; r++) {
                s[ch][r] += __shfl_xor_sync(0xFFFFFFFFu, s[ch][r], 1);
                s[ch][r] += __shfl_xor_sync(0xFFFFFFFFu, s[ch][r], 2);
            }
        float v0 = (q2 == 0) ? s[0][0] : (q2 == 1) ? s[1][0] : (q2 == 2) ? s[2][0] : s[3][0];
        float v1 = (q2 == 0) ? s[0][1] : (q2 == 1) ? s[1][1] : (q2 == 2) ? s[2][1] : s[3][1];

        long gp = P0 + wm + mf * 16 + (l >> 2);
        int b   = (int)(gp >> 14);
        int pin = (int)(gp & 16383);
        int ch  = cb + q2;
        float* o = out + ((size_t)b * 64 + ch) * 16384 + pin;
        o[0] = expf(-3.125f * v0);
        o[8] = expf(-3.125f * v1);
    }
}

// -------- launch ----------------------------------------------------------------
extern "C" void kernel_launch(void* const* d_in, const int* in_sizes, int n_in,
                              void* d_out, int out_size)
{
    const float* feat = (const float*)d_in[0];   // [8, 512, 128, 128]
    const float* wgt  = (const float*)d_in[1];   // [16, 64, 512]
    const float* m    = (const float*)d_in[2];   // [16, 64]
    const float* N    = (const float*)d_in[3];   // [64]
    float* out        = (float*)d_out;           // [8, 64, 128, 128]

    cudaFuncSetAttribute(duq_mma, cudaFuncAttributeMaxDynamicSharedMemorySize, SMEM_TOTAL);

    prep_feat<<<dim3(512, 8, 8), dim3(32, 8)>>>(feat);
    prep_w<<<1024, 128>>>(wgt, m, N);
    duq_mma<<<dim3(8, 1024), 256, SMEM_TOTAL>>>(out);
}

// round 9
// speedup vs baseline: 1.2648x; 1.0027x over previous
#include <cuda_runtime.h>
#include <cuda_fp16.h>
#include <cstdint>
#include <math.h>

// ============================================================================
// DUQ head via HMMA 3xFP16-split GEMM, single-pass shared-operand form,
// occupancy-2 geometry (2 CTAs/SM), product-major MMA ordering (acc dependency
// distance 4 instead of 1).
// out[b,c,p] = exp(-3.125 * sum_e (emb[p, c*16+e] - cent[c*16+e])^2)
// emb = feat[b,:,p].w[n,:], n=c*16+e, K=512.
// a = ah+al, b = bh+bl (exact fp16 splits); acc += ah*bh + ah*bl + al*bh (f32).
// CTA tile 128x128, warp tile 32x64 (8 warps/256 thr), BK=32,
// 3-stage cp.async, 32KB/stage -> 96KB smem, 2 CTAs/SM.
// ============================================================================

#define BM 128
#define BN 128
#define BK 32
#define KTILES 16            // 512 / 32
#define STAGE_BYTES 32768    // Ahi 8K | Alo 8K | Bhi 8K | Blo 8K
#define OFF_ALO 8192
#define OFF_BHI 16384
#define OFF_BLO 24576
#define CENT_OFF (3 * STAGE_BYTES)
#define SMEM_TOTAL (CENT_OFF + 512)

// -------- device-global scratch (no cudaMalloc allowed) ----------------------
__device__ __half g_ah[67108864];   // [131072 px][512 k]
__device__ __half g_al[67108864];
__device__ __half g_bh[524288];     // [1024 n][512 k], n = c*16+e
__device__ __half g_bl[524288];
__device__ float  g_cent[1024];

// -------- helpers -------------------------------------------------------------
__device__ __forceinline__ uint32_t smem_u32(const void* p) {
    uint32_t a;
    asm("{ .reg .u64 t; cvta.to.shared.u64 t, %1; cvt.u32.u64 %0, t; }" : "=r"(a) : "l"(p));
    return a;
}
__device__ __forceinline__ void cp16(uint32_t dst, const __half* src) {
    asm volatile("cp.async.cg.shared.global [%0], [%1], 16;"
                 :: "r"(dst), "l"(__cvta_generic_to_global(src)));
}
__device__ __forceinline__ void ldsm4(uint32_t* r, uint32_t addr) {
    asm volatile("ldmatrix.sync.aligned.m8n8.x4.shared.b16 {%0,%1,%2,%3}, [%4];"
                 : "=r"(r[0]), "=r"(r[1]), "=r"(r[2]), "=r"(r[3]) : "r"(addr));
}
__device__ __forceinline__ void mma_f32(float* c, const uint32_t* a, const uint32_t* b) {
    asm volatile("mma.sync.aligned.m16n8k16.row.col.f32.f16.f16.f32 "
                 "{%0,%1,%2,%3}, {%4,%5,%6,%7}, {%8,%9}, {%0,%1,%2,%3};"
                 : "+f"(c[0]), "+f"(c[1]), "+f"(c[2]), "+f"(c[3])
                 : "r"(a[0]), "r"(a[1]), "r"(a[2]), "r"(a[3]), "r"(b[0]), "r"(b[1]));
}

// -------- prep 1: transpose + fp16-split features (half2 coalesced writes) ----
__global__ void prep_feat(const float* __restrict__ feat) {
    __shared__ float tile[32][65];     // [p][k], padded
    int b  = blockIdx.z;
    int p0 = blockIdx.x * 32, k0 = blockIdx.y * 64;
    int tx = threadIdx.x, ty = threadIdx.y;                // (32, 8)
    const float* src = feat + ((size_t)b * 512 + k0) * 16384 + p0;
#pragma unroll
    for (int i = 0; i < 8; i++) {
        int kr = ty + 8 * i;
        tile[tx][kr] = src[(size_t)kr * 16384 + tx];
    }
    __syncthreads();
    size_t dbase = ((size_t)b * 16384 + p0) * 512 + k0;
#pragma unroll
    for (int j = 0; j < 4; j++) {
        int pr = ty + 8 * j;
        float v0 = tile[pr][2 * tx];
        float v1 = tile[pr][2 * tx + 1];
        __half h0 = __float2half_rn(v0);
        __half h1 = __float2half_rn(v1);
        __half l0 = __float2half_rn(v0 - __half2float(h0));
        __half l1 = __float2half_rn(v1 - __half2float(h1));
        size_t off = dbase + (size_t)pr * 512 + 2 * tx;
        *(__half2*)(g_ah + off) = __halves2half2(h0, h1);
        *(__half2*)(g_al + off) = __halves2half2(l0, l1);
    }
}

// -------- prep 2: weights reorder + split, centroids --------------------------
__global__ void prep_w(const float* __restrict__ wgt, const float* __restrict__ m,
                       const float* __restrict__ Nb) {
    int n = blockIdx.x;                 // n = c*16 + e
    int c = n >> 4, e = n & 15;
    const float* src = wgt + ((size_t)e * 64 + c) * 512;
    for (int k = threadIdx.x; k < 512; k += 128) {
        float v = src[k];
        __half hi = __float2half_rn(v);
        g_bh[(size_t)n * 512 + k] = hi;
        g_bl[(size_t)n * 512 + k] = __float2half_rn(v - __half2float(hi));
    }
    if (threadIdx.x == 0) g_cent[n] = m[e * 64 + c] / Nb[c];
}

// -------- stage fill (256 threads): 8 x 16B cp.async per thread ----------------
// 64B rows (4 chunks of 16B), swizzle chunk ^ ((row>>1)&3) -> ldsm conflict-free
__device__ __forceinline__ void fill_stage(uint32_t sb, int s, int kt, long P0, int n0, int t) {
    int kb = kt * BK;
    uint32_t st = sb + s * STAGE_BYTES;
    int r = t >> 2, c = t & 3;
#pragma unroll
    for (int i = 0; i < 2; i++) {
        int rr = r + i * 64;
        uint32_t d = st + rr * 64 + (uint32_t)((c ^ ((rr >> 1) & 3)) << 4);
        size_t asrc = (size_t)(P0 + rr) * 512 + kb + c * 8;
        size_t bsrc = (size_t)(n0 + rr) * 512 + kb + c * 8;
        cp16(d,           g_ah + asrc);
        cp16(d + OFF_ALO, g_al + asrc);
        cp16(d + OFF_BHI, g_bh + bsrc);
        cp16(d + OFF_BLO, g_bl + bsrc);
    }
}

// -------- main GEMM + fused RBF epilogue ---------------------------------------
__global__ __launch_bounds__(256, 2) void duq_mma(float* __restrict__ out) {
    extern __shared__ char smem[];
    uint32_t sb = smem_u32(smem);
    int t = threadIdx.x, l = t & 31, w = t >> 5;
    int nb = blockIdx.x, mb = blockIdx.y;
    long P0 = (long)mb * BM;           // 128 | 16384 -> never crosses a batch
    int n0 = nb * BN;

    if (t < BN) ((float*)(smem + CENT_OFF))[t] = g_cent[n0 + t];

    int wm = (w >> 1) * 32;            // 4 M-groups of 32
    int wn = (w & 1) * 64;             // 2 N-groups of 64

    int rl  = l & 7;                   // row within 8-row matrix
    int mh  = (l >> 3) & 1;            // matrix half bit
    int hi  = (l >> 4) & 1;            // k-chunk bit

    float acc[2][8][4];
#pragma unroll
    for (int i = 0; i < 2; i++)
#pragma unroll
        for (int j = 0; j < 8; j++)
#pragma unroll
            for (int q = 0; q < 4; q++) acc[i][j][q] = 0.0f;

    fill_stage(sb, 0, 0, P0, n0, t);
    asm volatile("cp.async.commit_group;" ::: "memory");
    fill_stage(sb, 1, 1, P0, n0, t);
    asm volatile("cp.async.commit_group;" ::: "memory");

    for (int kt = 0; kt < KTILES; kt++) {
        asm volatile("cp.async.wait_group 1;" ::: "memory");
        __syncthreads();

        if (kt + 2 < KTILES) fill_stage(sb, (kt + 2) % 3, kt + 2, P0, n0, t);
        asm volatile("cp.async.commit_group;" ::: "memory");

        uint32_t As = sb + (kt % 3) * STAGE_BYTES;
#pragma unroll
        for (int k16 = 0; k16 < 2; k16++) {
            uint32_t ah[2][4], al[2][4];
#pragma unroll
            for (int mf = 0; mf < 2; mf++) {
                int ra = wm + mf * 16 + mh * 8 + rl;
                uint32_t off = (uint32_t)(ra * 64 + (((2 * k16 + hi) ^ ((ra >> 1) & 3)) << 4));
                ldsm4(ah[mf], As + off);
                ldsm4(al[mf], As + OFF_ALO + off);
            }
#pragma unroll
            for (int np = 0; np < 4; np++) {
                int rb = wn + np * 16 + hi * 8 + rl;
                uint32_t off = (uint32_t)(rb * 64 + (((2 * k16 + mh) ^ ((rb >> 1) & 3)) << 4));
                uint32_t bh4[4], bl4[4];
                ldsm4(bh4, As + OFF_BHI + off);
                ldsm4(bl4, As + OFF_BLO + off);
                // product-major order: 4 independent MMAs per product group ->
                // acc RAW dependency distance = 4 instructions (was 1).
#pragma unroll
                for (int mf = 0; mf < 2; mf++)
#pragma unroll
                    for (int h = 0; h < 2; h++)
                        mma_f32(acc[mf][2 * np + h], ah[mf], &bh4[2 * h]);
#pragma unroll
                for (int mf = 0; mf < 2; mf++)
#pragma unroll
                    for (int h = 0; h < 2; h++)
                        mma_f32(acc[mf][2 * np + h], ah[mf], &bl4[2 * h]);
#pragma unroll
                for (int mf = 0; mf < 2; mf++)
#pragma unroll
                    for (int h = 0; h < 2; h++)
                        mma_f32(acc[mf][2 * np + h], al[mf], &bh4[2 * h]);
            }
        }
    }

    // ---- epilogue: diff^2, 16-e reduction (2 quad shuffles), __expf, store ----
    const float* centS = (const float*)(smem + CENT_OFF);
    int q2 = l & 3;
    int cb = (n0 + wn) >> 4;           // first of this warp's 4 channels

#pragma unroll
    for (int mf = 0; mf < 2; mf++) {
        float s[4][2];
#pragma unroll
        for (int ch = 0; ch < 4; ch++) { s[ch][0] = 0.0f; s[ch][1] = 0.0f; }
#pragma unroll
        for (int nf = 0; nf < 8; nf++) {
            int ch = nf >> 1;
#pragma unroll
            for (int j = 0; j < 2; j++) {
                float ce = centS[wn + nf * 8 + 2 * q2 + j];
                float d0 = acc[mf][nf][j]     - ce;
                float d1 = acc[mf][nf][2 + j] - ce;
                s[ch][0] = fmaf(d0, d0, s[ch][0]);
                s[ch][1] = fmaf(d1, d1, s[ch][1]);
            }
        }
#pragma unroll
        for (int ch = 0; ch < 4; ch++)
#pragma unroll
            for (int r = 0; r < 2; r++) {
                s[ch][r] += __shfl_xor_sync(0xFFFFFFFFu, s[ch][r], 1);
                s[ch][r] += __shfl_xor_sync(0xFFFFFFFFu, s[ch][r], 2);
            }
        float v0 = (q2 == 0) ? s[0][0] : (q2 == 1) ? s[1][0] : (q2 == 2) ? s[2][0] : s[3][0];
        float v1 = (q2 == 0) ? s[0][1] : (q2 == 1) ? s[1][1] : (q2 == 2) ? s[2][1] : s[3][1];

        long gp = P0 + wm + mf * 16 + (l >> 2);
        int b   = (int)(gp >> 14);
        int pin = (int)(gp & 16383);
        int ch  = cb + q2;
        float* o = out + ((size_t)b * 64 + ch) * 16384 + pin;
        o[0] = __expf(-3.125f * v0);
        o[8] = __expf(-3.125f * v1);
    }
}

// -------- launch ----------------------------------------------------------------
extern "C" void kernel_launch(void* const* d_in, const int* in_sizes, int n_in,
                              void* d_out, int out_size)
{
    const float* feat = (const float*)d_in[0];   // [8, 512, 128, 128]
    const float* wgt  = (const float*)d_in[1];   // [16, 64, 512]
    const float* m    = (const float*)d_in[2];   // [16, 64]
    const float* N    = (const float*)d_in[3];   // [64]
    float* out        = (float*)d_out;           // [8, 64, 128, 128]

    cudaFuncSetAttribute(duq_mma, cudaFuncAttributeMaxDynamicSharedMemorySize, SMEM_TOTAL);

    prep_feat<<<dim3(512, 8, 8), dim3(32, 8)>>>(feat);
    prep_w<<<1024, 128>>>(wgt, m, N);
    duq_mma<<<dim3(8, 1024), 256, SMEM_TOTAL>>>(out);
}